// round 7
// baseline (speedup 1.0000x reference)
#include <cuda_runtime.h>
#include <cuda_bf16.h>
#include <cstdint>

#define DINL __device__ __forceinline__

// B=512, D=256, O=256, H=[512,1024,1024]
// out[b,o] = b_b[o] + sum_h x3[b,h]*W_b[o,h] + sum_d iv[b,d]*b_d[d*256+o]
//          + sum_{d,h} iv[b,d]*x3[b,h]*W_d[d*256+o, h]
// Main + comp_b via warp-specialized bf16 mma.sync (hi/lo 3-GEMM split).

__device__ float g_x1[512 * 512];
__device__ float g_x2[512 * 1024];
__device__ float g_x3[512 * 1024];
__device__ float g_part[16 * 512 * 256];   // split-K partials [z][b][o]

DINL uint32_t s2u(const void* p) {
    uint32_t a;
    asm("{ .reg .u64 t; cvta.to.shared.u64 t, %1; cvt.u32.u64 %0, t; }"
        : "=r"(a) : "l"(p));
    return a;
}
// pack: low half = bf16(e0), high half = bf16(e1)
DINL uint32_t bfpack(float e0, float e1) {
    uint32_t r;
    asm("cvt.rn.bf16x2.f32 %0, %1, %2;" : "=r"(r) : "f"(e1), "f"(e0));
    return r;
}
DINL void ldsm4(uint32_t* r, uint32_t a) {
    asm volatile("ldmatrix.sync.aligned.m8n8.x4.shared.b16 {%0,%1,%2,%3}, [%4];"
                 : "=r"(r[0]), "=r"(r[1]), "=r"(r[2]), "=r"(r[3]) : "r"(a));
}
DINL void mma16816(float* c, const uint32_t* a, const uint32_t* b) {
    asm volatile(
        "mma.sync.aligned.m16n8k16.row.col.f32.bf16.bf16.f32 "
        "{%0,%1,%2,%3}, {%4,%5,%6,%7}, {%8,%9}, {%0,%1,%2,%3};"
        : "+f"(c[0]), "+f"(c[1]), "+f"(c[2]), "+f"(c[3])
        : "r"(a[0]), "r"(a[1]), "r"(a[2]), "r"(a[3]), "r"(b[0]), "r"(b[1]));
}
DINL void mbar_init(uint32_t a, uint32_t cnt) {
    asm volatile("mbarrier.init.shared.b64 [%0], %1;" :: "r"(a), "r"(cnt) : "memory");
}
DINL void mwait(uint32_t a, int ph) {
    asm volatile(
        "{\n\t.reg .pred P;\n\t"
        "WL%=:\n\t"
        "mbarrier.try_wait.parity.acquire.cta.shared::cta.b64 P, [%0], %1, 0x989680;\n\t"
        "@!P bra WL%=;\n\t}"
        :: "r"(a), "r"(ph) : "memory");
}
DINL void marrive(uint32_t a) {
    asm volatile("mbarrier.arrive.release.cta.shared::cta.b64 _, [%0];"
                 :: "r"(a) : "memory");
}
// split 8 fp32 -> bf16 hi (uint4) + bf16 lo residual (uint4)
DINL void split8(float4 f0, float4 f1, uint4& hi, uint4& lo) {
    hi.x = bfpack(f0.x, f0.y); hi.y = bfpack(f0.z, f0.w);
    hi.z = bfpack(f1.x, f1.y); hi.w = bfpack(f1.z, f1.w);
    lo.x = bfpack(f0.x - __uint_as_float(hi.x << 16),
                  f0.y - __uint_as_float(hi.x & 0xFFFF0000u));
    lo.y = bfpack(f0.z - __uint_as_float(hi.y << 16),
                  f0.w - __uint_as_float(hi.y & 0xFFFF0000u));
    lo.z = bfpack(f1.x - __uint_as_float(hi.z << 16),
                  f1.y - __uint_as_float(hi.z & 0xFFFF0000u));
    lo.w = bfpack(f1.z - __uint_as_float(hi.w << 16),
                  f1.w - __uint_as_float(hi.w & 0xFFFF0000u));
}

// ring: 4 stages; per stage A/B hi/lo tiles, 128 rows x 16 k, row stride 24 el
static constexpr int RST = 24;                       // row stride (el)
static constexpr int TILE_EL = 128 * RST;            // 3072
static constexpr int OAHI = 0, OALO = TILE_EL, OBHI = 2 * TILE_EL, OBLO = 3 * TILE_EL;
static constexpr int BUF_EL = 4 * TILE_EL;           // 12288 el
static constexpr int BUF_BYTES = BUF_EL * 2;         // 24576 B
static constexpr int NSTG = 4;
static constexpr int DSMEM_BYTES = NSTG * BUF_BYTES; // 98304 B

// ---------------------------------------------------------------------------
// Warp-specialized main contraction. Grid (m=4, n=2, z=16), 512 threads.
// Warps 0-7 producers, 8-15 consumers (each a 32x64 output tile).
// K per CTA = 16*1024 (+1024 Wb fold at z==0), stages of K=16.
// ---------------------------------------------------------------------------
__global__ __launch_bounds__(512, 1) void main_mma_kernel(
    const float* __restrict__ iv, const float* __restrict__ Wd,
    const float* __restrict__ Wb, const float* __restrict__ x3)
{
    extern __shared__ __align__(16) __nv_bfloat16 sm[];
    __shared__ __align__(8) unsigned long long mb[2 * NSTG];  // full[4], empty[4]

    const int tid = threadIdx.x, lane = tid & 31, wid = tid >> 5;
    const int m0 = blockIdx.x * 128, n0 = blockIdx.y * 128, z = blockIdx.z;
    const int nst = ((z == 0) ? 17 : 16) * 64;
    const uint32_t smu = s2u(sm);
    const uint32_t mbu = s2u(mb);

    if (tid < NSTG) {
        mbar_init(mbu + tid * 8, 8);            // full[s]
        mbar_init(mbu + (NSTG + tid) * 8, 8);   // empty[s]
    }
    __syncthreads();

    if (wid < 8) {
        // ================= PRODUCER =================
        const int rowH = tid >> 1;          // 0..127
        const int k8 = (tid & 1) * 8;
        float4 aF0, aF1, bF0, bF1;
        float ivv;

        auto ldg_stage = [&](int s) {
            int g = s >> 6, h0 = (s & 63) * 16;
            const float* Wbase;
            if (g < 16) {
                Wbase = Wd + ((size_t)((z * 16 + g) * 256 + n0)) * 1024;
                ivv = __ldg(iv + (size_t)(m0 + rowH) * 256 + (z * 16 + g));
            } else {
                Wbase = Wb + (size_t)n0 * 1024;
                ivv = 1.0f;
            }
            const float* xp = x3 + (size_t)(m0 + rowH) * 1024 + h0 + k8;
            aF0 = *(const float4*)xp; aF1 = *(const float4*)(xp + 4);
            const float* wp = Wbase + (size_t)rowH * 1024 + h0 + k8;
            bF0 = *(const float4*)wp; bF1 = *(const float4*)(wp + 4);
        };
        ldg_stage(0);

        int stg = 0, ph = 1;   // fresh empty barrier: parity-1 wait passes
        const int rowoff = rowH * RST + k8;
        for (int s = 0; s < nst; ++s) {
            mwait(mbu + (NSTG + stg) * 8, ph);
            __nv_bfloat16* bp = sm + stg * BUF_EL;
            float4 a0 = aF0, a1 = aF1;
            a0.x *= ivv; a0.y *= ivv; a0.z *= ivv; a0.w *= ivv;
            a1.x *= ivv; a1.y *= ivv; a1.z *= ivv; a1.w *= ivv;
            uint4 hi, lo;
            split8(a0, a1, hi, lo);
            *(uint4*)(bp + OAHI + rowoff) = hi;
            *(uint4*)(bp + OALO + rowoff) = lo;
            split8(bF0, bF1, hi, lo);
            *(uint4*)(bp + OBHI + rowoff) = hi;
            *(uint4*)(bp + OBLO + rowoff) = lo;
            __syncwarp();
            if (lane == 0) marrive(mbu + stg * 8);
            if (s + 1 < nst) ldg_stage(s + 1);
            if (++stg == NSTG) { stg = 0; ph ^= 1; }
        }
    } else {
        // ================= CONSUMER =================
        const int c = wid - 8;
        const int crow0 = (c >> 1) * 32;      // 32-row block
        const int ncol0 = (c & 1) * 64;       // 64-col block
        // ldmatrix lane addressing (element offsets)
        const int arow = (lane & 7) + ((lane >> 3) & 1) * 8;
        const int akh = ((lane >> 4) & 1) * 8;
        const int brow = (lane & 7) + ((lane >> 4) & 1) * 8;
        const int bkh = ((lane >> 3) & 1) * 8;

        uint32_t aoffh[2], aoffl[2], boffh[4], boffl[4];
        #pragma unroll
        for (int t = 0; t < 2; t++) {
            int e = (crow0 + t * 16 + arow) * RST + akh;
            aoffh[t] = (uint32_t)(OAHI + e) * 2;
            aoffl[t] = (uint32_t)(OALO + e) * 2;
        }
        #pragma unroll
        for (int p = 0; p < 4; p++) {
            int e = (ncol0 + p * 16 + brow) * RST + bkh;
            boffh[p] = (uint32_t)(OBHI + e) * 2;
            boffl[p] = (uint32_t)(OBLO + e) * 2;
        }

        float acc[2][8][4] = {};
        uint32_t Ah[2][4], Al[2][4], Bf[4][4];

        int stg = 0, ph = 0;
        for (int s = 0; s < nst; ++s) {
            mwait(mbu + stg * 8, ph);
            const uint32_t base = smu + (uint32_t)stg * BUF_BYTES;
            #pragma unroll
            for (int p = 0; p < 4; p++) ldsm4(Bf[p], base + boffh[p]);
            #pragma unroll
            for (int t = 0; t < 2; t++) ldsm4(Ah[t], base + aoffh[t]);
            #pragma unroll
            for (int t = 0; t < 2; t++) ldsm4(Al[t], base + aoffl[t]);
            #pragma unroll
            for (int t = 0; t < 2; t++)
                #pragma unroll
                for (int p = 0; p < 4; p++) {
                    mma16816(acc[t][p * 2 + 0], Ah[t], &Bf[p][0]);
                    mma16816(acc[t][p * 2 + 1], Ah[t], &Bf[p][2]);
                    mma16816(acc[t][p * 2 + 0], Al[t], &Bf[p][0]);
                    mma16816(acc[t][p * 2 + 1], Al[t], &Bf[p][2]);
                }
            #pragma unroll
            for (int p = 0; p < 4; p++) ldsm4(Bf[p], base + boffl[p]);
            #pragma unroll
            for (int t = 0; t < 2; t++)
                #pragma unroll
                for (int p = 0; p < 4; p++) {
                    mma16816(acc[t][p * 2 + 0], Ah[t], &Bf[p][0]);
                    mma16816(acc[t][p * 2 + 1], Ah[t], &Bf[p][2]);
                }
            __syncwarp();
            if (lane == 0) marrive(mbu + (NSTG + stg) * 8);
            if (++stg == NSTG) { stg = 0; ph ^= 1; }
        }

        // epilogue: split-K partials
        float* part = g_part + (size_t)z * (512 * 256);
        #pragma unroll
        for (int t = 0; t < 2; t++) {
            int mr = m0 + crow0 + t * 16 + (lane >> 2);
            #pragma unroll
            for (int p8 = 0; p8 < 8; p8++) {
                int nc = n0 + ncol0 + p8 * 8 + (lane & 3) * 2;
                *(float2*)(part + (size_t)mr * 256 + nc) =
                    make_float2(acc[t][p8][0], acc[t][p8][1]);
                *(float2*)(part + (size_t)(mr + 8) * 256 + nc) =
                    make_float2(acc[t][p8][2], acc[t][p8][3]);
            }
        }
    }
}

// ---------------------------------------------------------------------------
// MLP layer: C = relu(A @ W^T + bias)   (fp32 SIMT)
// ---------------------------------------------------------------------------
__global__ __launch_bounds__(256) void mlp_layer_kernel(
    const float* __restrict__ A, const float* __restrict__ W,
    const float* __restrict__ bias, float* __restrict__ C,
    int M, int N, int K)
{
    __shared__ float a_s[16][68];
    __shared__ float w_s[16][68];
    int m0 = blockIdx.y * 64, n0 = blockIdx.x * 64;
    int tid = threadIdx.x;
    int tx = tid & 15, ty = tid >> 4;
    int lrow = tid >> 2, lk = (tid & 3) * 4;
    float acc[4][4] = {};

    for (int k0 = 0; k0 < K; k0 += 16) {
        float4 av = *(const float4*)(A + (size_t)(m0 + lrow) * K + k0 + lk);
        float4 wv = *(const float4*)(W + (size_t)(n0 + lrow) * K + k0 + lk);
        a_s[lk + 0][lrow] = av.x; a_s[lk + 1][lrow] = av.y;
        a_s[lk + 2][lrow] = av.z; a_s[lk + 3][lrow] = av.w;
        w_s[lk + 0][lrow] = wv.x; w_s[lk + 1][lrow] = wv.y;
        w_s[lk + 2][lrow] = wv.z; w_s[lk + 3][lrow] = wv.w;
        __syncthreads();
        #pragma unroll
        for (int kk = 0; kk < 16; kk++) {
            float4 ra = *(const float4*)&a_s[kk][ty * 4];
            float4 rb = *(const float4*)&w_s[kk][tx * 4];
            float ar[4] = {ra.x, ra.y, ra.z, ra.w};
            float br[4] = {rb.x, rb.y, rb.z, rb.w};
            #pragma unroll
            for (int i = 0; i < 4; i++)
                #pragma unroll
                for (int j = 0; j < 4; j++)
                    acc[i][j] += ar[i] * br[j];
        }
        __syncthreads();
    }
    #pragma unroll
    for (int i = 0; i < 4; i++) {
        int m = m0 + ty * 4 + i;
        #pragma unroll
        for (int j = 0; j < 4; j++) {
            int n = n0 + tx * 4 + j;
            float v = acc[i][j] + bias[n];
            C[(size_t)m * N + n] = v > 0.f ? v : 0.f;
        }
    }
}

// ---------------------------------------------------------------------------
// out[b,o] = b_b[o] + sum_z part[z][b,o] + sum_d iv[b,d]*b_d[d*256+o]
// ---------------------------------------------------------------------------
__global__ __launch_bounds__(256) void reduce_kernel(
    const float* __restrict__ iv, const float* __restrict__ bd,
    const float* __restrict__ bb, float* __restrict__ out)
{
    __shared__ float sIv[256];
    int b = blockIdx.x;
    int o = threadIdx.x;
    sIv[o] = iv[(size_t)b * 256 + o];
    __syncthreads();
    size_t idx = (size_t)b * 256 + o;
    float s = bb[o];
    #pragma unroll 8
    for (int z = 0; z < 16; z++)
        s += g_part[(size_t)z * 131072 + idx];
    #pragma unroll 8
    for (int d = 0; d < 256; d++)
        s = fmaf(sIv[d], bd[d * 256 + o], s);
    out[idx] = s;
}

extern "C" void kernel_launch(void* const* d_in, const int* in_sizes, int n_in,
                              void* d_out, int out_size)
{
    const float* IV = (const float*)d_in[0];   // input_values [512,256]
    const float* NF = (const float*)d_in[1];   // nan_flag     [512,256]
    int base = (in_sizes[2] == 512 * 256) ? 2 : 3;   // skip `training` if present
    const float* W_in = (const float*)d_in[base + 0];  // [512,256]
    const float* b_in = (const float*)d_in[base + 1];  // [512]
    const float* W_h1 = (const float*)d_in[base + 2];  // [1024,512]
    const float* b_h1 = (const float*)d_in[base + 3];  // [1024]
    const float* W_h2 = (const float*)d_in[base + 4];  // [1024,1024]
    const float* b_h2 = (const float*)d_in[base + 5];  // [1024]
    const float* W_d  = (const float*)d_in[base + 6];  // [65536,1024]
    const float* b_d  = (const float*)d_in[base + 7];  // [65536]
    const float* W_b  = (const float*)d_in[base + 8];  // [256,1024]
    const float* b_b  = (const float*)d_in[base + 9];  // [256]
    float* out = (float*)d_out;

    float *x1, *x2, *x3;
    cudaGetSymbolAddress((void**)&x1, g_x1);
    cudaGetSymbolAddress((void**)&x2, g_x2);
    cudaGetSymbolAddress((void**)&x3, g_x3);

    cudaFuncSetAttribute(main_mma_kernel,
                         cudaFuncAttributeMaxDynamicSharedMemorySize, DSMEM_BYTES);

    // MLP
    mlp_layer_kernel<<<dim3(8, 8), 256>>>(NF, W_in, b_in, x1, 512, 512, 256);
    mlp_layer_kernel<<<dim3(16, 8), 256>>>(x1, W_h1, b_h1, x2, 512, 1024, 512);
    mlp_layer_kernel<<<dim3(16, 8), 256>>>(x2, W_h2, b_h2, x3, 512, 1024, 1024);

    // Warp-specialized main contraction (+ W_b fold at z==0)
    main_mma_kernel<<<dim3(4, 2, 16), 512, DSMEM_BYTES>>>(IV, W_d, W_b, x3);

    // Deterministic split-K reduce + bias terms
    reduce_kernel<<<dim3(512), 256>>>(IV, b_d, b_b, out);
}